// round 1
// baseline (speedup 1.0000x reference)
#include <cuda_runtime.h>

#define NQ   2048
#define NS   320
#define DIM  256
#define NWAY 20

// Scratch (allocation-free rule: device globals)
__device__ float g_qproj[NQ * DIM];   // query @ W1[:256]
__device__ float g_sproj[NS * DIM];   // support @ W1[256:] + b1

// ---------------------------------------------------------------------------
// Kernel A: projections (SIMT fp32 GEMM, 64x64x16 tiles, 4x4 microtile)
// Rows [0,2048): query * W1[0:256]; tiles >=32: support * W1[256:512] + b1
// ---------------------------------------------------------------------------
#define BM 64
#define BN 64
#define BK 16
#define LDA 68   // padded

__global__ void __launch_bounds__(256) proj_kernel(
    const float* __restrict__ support, const float* __restrict__ query,
    const float* __restrict__ W1, const float* __restrict__ b1)
{
    __shared__ float As[BK][LDA];   // [k][m]
    __shared__ float Bs[BK][LDA];   // [k][n]

    const int tile_n = blockIdx.x;
    const int tile_m = blockIdx.y;
    const bool is_sup = (tile_m >= NQ / BM);

    const float* Amat;
    const float* Bmat;
    int m0;
    if (is_sup) { m0 = (tile_m - NQ / BM) * BM; Amat = support; Bmat = W1 + DIM * DIM; }
    else        { m0 = tile_m * BM;             Amat = query;   Bmat = W1; }
    const int n0 = tile_n * BN;

    const int tid = threadIdx.x;
    const int tx = tid & 15;        // n-direction
    const int ty = tid >> 4;        // m-direction

    const int arow = tid >> 2;      // 0..63
    const int ak4  = tid & 3;       // 0..3  (k-group of 4)
    const int brow = tid >> 4;      // 0..15 (k)
    const int bc4  = tid & 15;      // 0..15 (n-group of 4)

    float acc[4][4];
    #pragma unroll
    for (int i = 0; i < 4; i++)
        #pragma unroll
        for (int j = 0; j < 4; j++) acc[i][j] = 0.f;

    for (int k0 = 0; k0 < DIM; k0 += BK) {
        float4 av = *(const float4*)(Amat + (m0 + arow) * DIM + k0 + ak4 * 4);
        As[ak4 * 4 + 0][arow] = av.x;
        As[ak4 * 4 + 1][arow] = av.y;
        As[ak4 * 4 + 2][arow] = av.z;
        As[ak4 * 4 + 3][arow] = av.w;
        float4 bv = *(const float4*)(Bmat + (k0 + brow) * DIM + n0 + bc4 * 4);
        *(float4*)&Bs[brow][bc4 * 4] = bv;
        __syncthreads();

        #pragma unroll
        for (int k = 0; k < BK; k++) {
            float4 a = *(const float4*)&As[k][ty * 4];
            float4 b = *(const float4*)&Bs[k][tx * 4];
            acc[0][0] = fmaf(a.x, b.x, acc[0][0]);
            acc[0][1] = fmaf(a.x, b.y, acc[0][1]);
            acc[0][2] = fmaf(a.x, b.z, acc[0][2]);
            acc[0][3] = fmaf(a.x, b.w, acc[0][3]);
            acc[1][0] = fmaf(a.y, b.x, acc[1][0]);
            acc[1][1] = fmaf(a.y, b.y, acc[1][1]);
            acc[1][2] = fmaf(a.y, b.z, acc[1][2]);
            acc[1][3] = fmaf(a.y, b.w, acc[1][3]);
            acc[2][0] = fmaf(a.z, b.x, acc[2][0]);
            acc[2][1] = fmaf(a.z, b.y, acc[2][1]);
            acc[2][2] = fmaf(a.z, b.z, acc[2][2]);
            acc[2][3] = fmaf(a.z, b.w, acc[2][3]);
            acc[3][0] = fmaf(a.w, b.x, acc[3][0]);
            acc[3][1] = fmaf(a.w, b.y, acc[3][1]);
            acc[3][2] = fmaf(a.w, b.z, acc[3][2]);
            acc[3][3] = fmaf(a.w, b.w, acc[3][3]);
        }
        __syncthreads();
    }

    #pragma unroll
    for (int i = 0; i < 4; i++) {
        const int m = m0 + ty * 4 + i;
        #pragma unroll
        for (int j = 0; j < 4; j++) {
            const int n = n0 + tx * 4 + j;
            float v = acc[i][j];
            if (is_sup) g_sproj[m * DIM + n] = v + __ldg(b1 + n);
            else        g_qproj[m * DIM + n] = v;
        }
    }
}

// ---------------------------------------------------------------------------
// Kernel B: scores + softmax + one-hot aggregation
// Block: 16 q (8 warps x 2 q/warp), lanes = 32 s within a chunk, 10 chunks.
// sp chunks double-buffered via cp.async; rows padded to 260 floats.
// ---------------------------------------------------------------------------
#define QB 16
#define SPAD 260
#define NCHUNK 10
#define CHUNK_F4 2048   // 32 rows * 64 float4 per chunk

__device__ __forceinline__ void cpa16(float* dst, const float* src) {
    unsigned sa = (unsigned)__cvta_generic_to_shared(dst);
    asm volatile("cp.async.cg.shared.global [%0], [%1], 16;" :: "r"(sa), "l"(src));
}

__device__ __forceinline__ void prefetch_chunk(float* buf, int c, int tid) {
    #pragma unroll
    for (int i = 0; i < 8; i++) {
        int f   = tid + i * 256;   // float4 index 0..2047
        int row = f >> 6;          // 0..31
        int c4  = f & 63;          // 0..63
        cpa16(buf + row * SPAD + c4 * 4, g_sproj + (c * 32 + row) * DIM + c4 * 4);
    }
    asm volatile("cp.async.commit_group;");
}

__global__ void __launch_bounds__(256) score_kernel(
    const int* __restrict__ labels, const float* __restrict__ W2,
    float* __restrict__ out)
{
    extern __shared__ float sm[];
    float* sp0  = sm;                       // 8320 floats
    float* sp1  = sm + 8320;                // 8320
    float* qp   = sm + 2 * 8320;            // QB*256 = 4096
    float* w2s  = qp + QB * DIM;            // 256
    float* sacc = w2s + DIM;                // QB*20 = 320
    int*   lbl  = (int*)(sacc + QB * NWAY); // 320 ints

    const int tid  = threadIdx.x;
    const int warp = tid >> 5;
    const int lane = tid & 31;
    const int qbase = blockIdx.x * QB;

    // prefetch first sp chunk
    prefetch_chunk(sp0, 0, tid);

    // regular initial loads
    {
        const float4* src = (const float4*)(g_qproj + qbase * DIM);
        #pragma unroll
        for (int i = 0; i < QB * DIM / 4 / 256; i++)
            ((float4*)qp)[tid + i * 256] = src[tid + i * 256];
        if (tid < DIM / 4) ((float4*)w2s)[tid] = ((const float4*)W2)[tid];
        for (int i = tid; i < NS; i += 256) lbl[i] = labels[i];
        for (int i = tid; i < QB * NWAY; i += 256) sacc[i] = 0.f;
    }

    float sc[2][NCHUNK];
    const float4* qa4 = (const float4*)(qp + (warp * 2) * DIM);
    const float4* qb4 = (const float4*)(qp + (warp * 2 + 1) * DIM);
    const float4* w24 = (const float4*)w2s;

    float* spb0 = sp0;
    float* spb1 = sp1;

    for (int c = 0; c < NCHUNK; c++) {
        asm volatile("cp.async.wait_group 0;");
        __syncthreads();
        float* cur = (c & 1) ? spb1 : spb0;
        if (c + 1 < NCHUNK) prefetch_chunk((c & 1) ? spb0 : spb1, c + 1, tid);

        const float4* srow = (const float4*)(cur + lane * SPAD);
        float s0 = 0.f, s1 = 0.f;
        #pragma unroll 8
        for (int d = 0; d < DIM / 4; d++) {
            float4 sv = srow[d];
            float4 a  = qa4[d];
            float4 b  = qb4[d];
            float4 w  = w24[d];
            s0 = fmaf(fmaxf(a.x + sv.x, 0.f), w.x, s0);
            s0 = fmaf(fmaxf(a.y + sv.y, 0.f), w.y, s0);
            s0 = fmaf(fmaxf(a.z + sv.z, 0.f), w.z, s0);
            s0 = fmaf(fmaxf(a.w + sv.w, 0.f), w.w, s0);
            s1 = fmaf(fmaxf(b.x + sv.x, 0.f), w.x, s1);
            s1 = fmaf(fmaxf(b.y + sv.y, 0.f), w.y, s1);
            s1 = fmaf(fmaxf(b.z + sv.z, 0.f), w.z, s1);
            s1 = fmaf(fmaxf(b.w + sv.w, 0.f), w.w, s1);
        }
        sc[0][c] = s0;
        sc[1][c] = s1;
    }

    // ---- softmax over 320 support + one-hot class aggregation ----
    float invl[2];
    #pragma unroll
    for (int j = 0; j < 2; j++) {
        float m = sc[j][0];
        #pragma unroll
        for (int i = 1; i < NCHUNK; i++) m = fmaxf(m, sc[j][i]);
        #pragma unroll
        for (int o = 16; o > 0; o >>= 1)
            m = fmaxf(m, __shfl_xor_sync(0xffffffffu, m, o));

        float e[NCHUNK];
        float l = 0.f;
        #pragma unroll
        for (int i = 0; i < NCHUNK; i++) { e[i] = __expf(sc[j][i] - m); l += e[i]; }
        #pragma unroll
        for (int o = 16; o > 0; o >>= 1)
            l += __shfl_xor_sync(0xffffffffu, l, o);
        invl[j] = 1.f / l;

        float* accq = sacc + (warp * 2 + j) * NWAY;
        #pragma unroll
        for (int i = 0; i < NCHUNK; i++)
            atomicAdd(&accq[lbl[i * 32 + lane]], e[i]);
    }
    __syncthreads();

    if (lane < NWAY) {
        const int q0 = qbase + warp * 2;
        out[q0 * NWAY + lane]       = sacc[(warp * 2) * NWAY + lane] * invl[0];
        out[(q0 + 1) * NWAY + lane] = sacc[(warp * 2 + 1) * NWAY + lane] * invl[1];
    }
}

// ---------------------------------------------------------------------------
extern "C" void kernel_launch(void* const* d_in, const int* in_sizes, int n_in,
                              void* d_out, int out_size)
{
    (void)in_sizes; (void)n_in; (void)out_size;
    const float* support = (const float*)d_in[0];
    const float* query   = (const float*)d_in[1];
    const int*   labels  = (const int*)d_in[2];
    const float* W1      = (const float*)d_in[3];
    const float* b1      = (const float*)d_in[4];
    const float* W2      = (const float*)d_in[5];
    float* out = (float*)d_out;

    // Kernel A: 4 n-tiles x 37 m-tiles (32 query + 5 support) = 148 blocks
    proj_kernel<<<dim3(4, 37), 256>>>(support, query, W1, b1);

    const int smem_bytes = (2 * 8320 + QB * DIM + DIM + QB * NWAY) * 4 + NS * 4;
    cudaFuncSetAttribute(score_kernel,
                         cudaFuncAttributeMaxDynamicSharedMemorySize, smem_bytes);
    score_kernel<<<NQ / QB, 256, smem_bytes>>>(labels, W2, out);
}